// round 6
// baseline (speedup 1.0000x reference)
#include <cuda_runtime.h>
#include <cuda_bf16.h>
#include <cstdint>
#include <math.h>

#define Bz 64
#define Pz 196
#define Dz 512
#define Vz 10000
#define MAXLEN 52
#define Tz 51
#define G4 2048

#define MPAD 3328          // 26*128 (pad of 3264)
#define NPAD_FC 10112      // 79*128

typedef long long ll;

static const ll OFF_CAPS = (ll)Bz * Tz * Vz;
static const ll OFF_DEC  = OFF_CAPS + (ll)Bz * MAXLEN;
static const ll OFF_SI   = OFF_DEC + Bz;

// ------------------------- device scratch ---------------------------------
__device__ float d_enc_s[Bz * Pz * Dz];
__device__ float d_att1[Bz * Pz * Dz];
__device__ float d_cls[Bz * Dz];
__device__ float d_h[Bz * Dz];
__device__ float d_c[Bz * Dz];
__device__ float d_hg[Bz * 1024];
__device__ float d_awe[Bz * Dz];
__device__ float d_pre[Tz * Bz * G4];
__device__ float d_clspre[Bz * G4];
__device__ float d_gates[Bz * G4];
__device__ float d_WihT[1536 * G4];
__device__ float d_WhhT[Dz * G4];
__device__ float d_biasc[G4];
__device__ int   d_sort[Bz];
__device__ int   d_dec[Bz];
__device__ int   d_caps[Bz * MAXLEN];

// bf16 hi/lo operand scratch for tensor-core GEMMs
__device__ __nv_bfloat16 d_encA_h[Bz * Pz * Dz];
__device__ __nv_bfloat16 d_encA_l[Bz * Pz * Dz];
__device__ __nv_bfloat16 d_embA_h[MPAD * Dz];
__device__ __nv_bfloat16 d_embA_l[MPAD * Dz];
__device__ __nv_bfloat16 d_HallA_h[MPAD * Dz];
__device__ __nv_bfloat16 d_HallA_l[MPAD * Dz];
__device__ __nv_bfloat16 d_attB_h[Dz * Dz];
__device__ __nv_bfloat16 d_attB_l[Dz * Dz];
__device__ __nv_bfloat16 d_wihB_h[G4 * Dz];
__device__ __nv_bfloat16 d_wihB_l[G4 * Dz];
__device__ __nv_bfloat16 d_fcB_h[(ll)NPAD_FC * Dz];
__device__ __nv_bfloat16 d_fcB_l[(ll)NPAD_FC * Dz];

__device__ __forceinline__ float sigf(float x) { return 1.f / (1.f + __expf(-x)); }

__device__ __forceinline__ uint32_t smem_u32(const void* p) {
    uint32_t a;
    asm("{ .reg .u64 t; cvta.to.shared.u64 t, %1; cvt.u32.u64 %0, t; }"
        : "=r"(a) : "l"(p));
    return a;
}

// ---- portable PTX (sm_80-era): mma.sync / ldmatrix / cp.async -------------
#define MMA_BF16(c, a, b0, b1) \
    asm volatile("mma.sync.aligned.m16n8k16.row.col.f32.bf16.bf16.f32 " \
        "{%0,%1,%2,%3}, {%4,%5,%6,%7}, {%8,%9}, {%0,%1,%2,%3};" \
        : "+f"((c)[0]), "+f"((c)[1]), "+f"((c)[2]), "+f"((c)[3]) \
        : "r"((a)[0]), "r"((a)[1]), "r"((a)[2]), "r"((a)[3]), "r"(b0), "r"(b1))

#define LDMX4(r, addr) \
    asm volatile("ldmatrix.sync.aligned.m8n8.x4.shared.b16 {%0,%1,%2,%3}, [%4];" \
        : "=r"((r)[0]), "=r"((r)[1]), "=r"((r)[2]), "=r"((r)[3]) : "r"(addr))

#define CPA16(s, g) \
    asm volatile("cp.async.cg.shared.global [%0], [%1], 16;" :: "r"(s), "l"(g))
#define CPA_COMMIT() asm volatile("cp.async.commit_group;" ::: "memory")
#define CPA_WAIT0()  asm volatile("cp.async.wait_group 0;" ::: "memory")
#define CPA_WAIT1()  asm volatile("cp.async.wait_group 1;" ::: "memory")

// ------------------------- setup kernels ----------------------------------
__global__ void k_sort(const int* __restrict__ cap_len, float* __restrict__ out,
                       ll out_size) {
    __shared__ int ls[Bz];
    int tid = threadIdx.x;
    ls[tid] = cap_len[tid];
    __syncthreads();
    int my = ls[tid];
    int rank = 0;
    for (int j = 0; j < Bz; j++) {
        int lj = ls[j];
        if (lj > my || (lj == my && j < tid)) rank++;
    }
    d_sort[rank] = tid;
    d_dec[rank]  = my - 1;
    if (OFF_SI + Bz <= out_size) {
        out[OFF_DEC + rank] = (float)(my - 1);
        out[OFF_SI + rank]  = (float)tid;
    }
}

__global__ void k_gather_enc(const float* __restrict__ enc_in) {
    int n = Bz * Pz * Dz;
    for (int idx = blockIdx.x * blockDim.x + threadIdx.x; idx < n;
         idx += gridDim.x * blockDim.x) {
        int b = idx / (Pz * Dz);
        int r = idx - b * (Pz * Dz);
        float v = enc_in[(ll)d_sort[b] * (Pz * Dz) + r];
        d_enc_s[idx] = v;
        __nv_bfloat16 h = __float2bfloat16(v);
        d_encA_h[idx] = h;
        d_encA_l[idx] = __float2bfloat16(v - __bfloat162float(h));
    }
}

__global__ void k_gather_misc(const int* __restrict__ caps_in,
                              const int* __restrict__ class_k,
                              const float* __restrict__ clsW,
                              float* __restrict__ out, ll out_size) {
    int b = blockIdx.x;
    int e = threadIdx.x;
    d_cls[b * Dz + e] = clsW[(ll)class_k[b] * Dz + e];
    if (e < MAXLEN) {
        int v = caps_in[d_sort[b] * MAXLEN + e];
        d_caps[b * MAXLEN + e] = v;
        if (OFF_CAPS + (ll)Bz * MAXLEN <= out_size)
            out[OFF_CAPS + b * MAXLEN + e] = (float)v;
    }
}

__global__ void k_init(const float* __restrict__ ihW, const float* __restrict__ ihb,
                       const float* __restrict__ icW, const float* __restrict__ icb) {
    __shared__ float s[1024];
    int b = blockIdx.x, j = threadIdx.x;
    float s0 = 0.f, s1 = 0.f, s2 = 0.f, s3 = 0.f;
#pragma unroll 4
    for (int p = 0; p < 196; p += 4) {
        s0 += d_enc_s[(b * Pz + p) * Dz + j];
        s1 += d_enc_s[(b * Pz + p + 1) * Dz + j];
        s2 += d_enc_s[(b * Pz + p + 2) * Dz + j];
        s3 += d_enc_s[(b * Pz + p + 3) * Dz + j];
    }
    s[j] = (s0 + s1 + s2 + s3) * (1.f / 196.f);
    s[Dz + j] = d_cls[b * Dz + j];
    __syncthreads();
    float ah0 = ihb[j], ah1 = 0.f, ac0 = icb[j], ac1 = 0.f;
#pragma unroll 4
    for (int k = 0; k < 1024; k += 2) {
        float x0 = s[k], x1 = s[k + 1];
        ah0 = fmaf(x0, ihW[k * Dz + j], ah0);
        ac0 = fmaf(x0, icW[k * Dz + j], ac0);
        ah1 = fmaf(x1, ihW[(k + 1) * Dz + j], ah1);
        ac1 = fmaf(x1, icW[(k + 1) * Dz + j], ac1);
    }
    d_h[b * Dz + j] = ah0 + ah1;
    d_c[b * Dz + j] = ac0 + ac1;
}

__global__ void k_embs(const float* __restrict__ embW) {
    int n = Tz * Bz * Dz;
    for (int idx = blockIdx.x * blockDim.x + threadIdx.x; idx < n;
         idx += gridDim.x * blockDim.x) {
        int r = idx / Dz, k = idx - r * Dz;
        int t = r >> 6, b = r & 63;
        int tok = d_caps[b * MAXLEN + t];
        float v = embW[(ll)tok * Dz + k];
        __nv_bfloat16 h = __float2bfloat16(v);
        d_embA_h[idx] = h;
        d_embA_l[idx] = __float2bfloat16(v - __bfloat162float(h));
    }
}

__global__ void k_padzero() {
    int n = (MPAD - Tz * Bz) * Dz;
    __nv_bfloat16 z = __float2bfloat16(0.f);
    for (int idx = blockIdx.x * blockDim.x + threadIdx.x; idx < n;
         idx += gridDim.x * blockDim.x) {
        int o = Tz * Bz * Dz + idx;
        d_embA_h[o] = z; d_embA_l[o] = z;
        d_HallA_h[o] = z; d_HallA_l[o] = z;
    }
}

__global__ void k_transpose(const float* __restrict__ Wih,
                            const float* __restrict__ Whh) {
    int n1 = 1536 * G4;
    int n = n1 + Dz * G4;
    for (int idx = blockIdx.x * blockDim.x + threadIdx.x; idx < n;
         idx += gridDim.x * blockDim.x) {
        if (idx < n1) {
            int k = idx / G4, j = idx - k * G4;
            d_WihT[idx] = Wih[(ll)j * 1536 + k];
        } else {
            int i2 = idx - n1;
            int k = i2 / G4, j = i2 - k * G4;
            d_WhhT[i2] = Whh[(ll)j * Dz + k];
        }
    }
}

__global__ void k_cvt_wih(const float* __restrict__ Wih) {
    int n = G4 * Dz;
    for (int idx = blockIdx.x * blockDim.x + threadIdx.x; idx < n;
         idx += gridDim.x * blockDim.x) {
        int j = idx / Dz, k = idx - j * Dz;
        float v = Wih[(ll)j * 1536 + k];
        __nv_bfloat16 h = __float2bfloat16(v);
        d_wihB_h[idx] = h;
        d_wihB_l[idx] = __float2bfloat16(v - __bfloat162float(h));
    }
}

// Transpose+convert: src [512 x N] -> dst [Npad x 512] hi/lo (zero-padded)
__global__ void k_cvtT(const float* __restrict__ src, int N,
                       __nv_bfloat16* __restrict__ dh, __nv_bfloat16* __restrict__ dl) {
    __shared__ float t[32][33];
    int n0 = blockIdx.x * 32, k0 = blockIdx.y * 32;
    int x = threadIdx.x, y = threadIdx.y;  // (32, 8)
    for (int i = y; i < 32; i += 8) {
        int k = k0 + i, n = n0 + x;
        t[i][x] = (n < N) ? src[(ll)k * N + n] : 0.f;
    }
    __syncthreads();
    for (int i = y; i < 32; i += 8) {
        int n = n0 + i, k = k0 + x;
        float v = t[x][i];
        __nv_bfloat16 h = __float2bfloat16(v);
        ll o = (ll)n * Dz + k;
        dh[o] = h;
        dl[o] = __float2bfloat16(v - __bfloat162float(h));
    }
}

__global__ void k_biasc(const float* __restrict__ bih, const float* __restrict__ bhh) {
    int j = blockIdx.x * 256 + threadIdx.x;
    if (j < G4) d_biasc[j] = bih[j] + bhh[j];
}

// ------------------------- SIMT GEMM (cls_pre only) ------------------------
__global__ void __launch_bounds__(256) gemm128(
    const float* __restrict__ A, int lda, const float* __restrict__ Bm, int ldb,
    const float* __restrict__ bias, float* __restrict__ C, int ldc,
    int M, int N, int K) {
    __shared__ float As[8][128];
    __shared__ float Bs[8][128];
    int tid = threadIdx.x;
    int n0 = blockIdx.x * 128, m0 = blockIdx.y * 128;
    int tx = tid & 15, ty = tid >> 4;
    float acc[8][8];
#pragma unroll
    for (int i = 0; i < 8; i++)
#pragma unroll
        for (int j = 0; j < 8; j++) acc[i][j] = 0.f;
    int lm = tid >> 1, lkq = (tid & 1) * 4, lk = tid >> 5, ln4 = (tid & 31) * 4;
    for (int k0 = 0; k0 < K; k0 += 8) {
        float4 va = make_float4(0.f, 0.f, 0.f, 0.f);
        int gm = m0 + lm;
        if (gm < M) va = *(const float4*)(A + (ll)gm * lda + k0 + lkq);
        float4 vb = make_float4(0.f, 0.f, 0.f, 0.f);
        int gn = n0 + ln4;
        if (gn + 3 < N) vb = *(const float4*)(Bm + (ll)(k0 + lk) * ldb + gn);
        __syncthreads();
        As[lkq + 0][lm] = va.x; As[lkq + 1][lm] = va.y;
        As[lkq + 2][lm] = va.z; As[lkq + 3][lm] = va.w;
        *(float4*)&Bs[lk][ln4] = vb;
        __syncthreads();
#pragma unroll
        for (int kk = 0; kk < 8; kk++) {
            float4 A0 = *(const float4*)&As[kk][ty * 8];
            float4 A1 = *(const float4*)&As[kk][ty * 8 + 4];
            float4 B0 = *(const float4*)&Bs[kk][tx * 8];
            float4 B1 = *(const float4*)&Bs[kk][tx * 8 + 4];
            float ar[8] = {A0.x, A0.y, A0.z, A0.w, A1.x, A1.y, A1.z, A1.w};
            float br[8] = {B0.x, B0.y, B0.z, B0.w, B1.x, B1.y, B1.z, B1.w};
#pragma unroll
            for (int i = 0; i < 8; i++)
#pragma unroll
                for (int j = 0; j < 8; j++) acc[i][j] = fmaf(ar[i], br[j], acc[i][j]);
        }
    }
#pragma unroll
    for (int i = 0; i < 8; i++) {
        int gm = m0 + ty * 8 + i;
        if (gm >= M) continue;
#pragma unroll
        for (int j = 0; j < 8; j++) {
            int gn = n0 + tx * 8 + j;
            if (gn >= N) continue;
            C[(ll)gm * ldc + gn] = acc[i][j] + (bias ? bias[gn] : 0.f);
        }
    }
}

// ------------------------- HMMA split-bf16 GEMM ----------------------------
// C[M,N] = (Ah+Al)[M,512] @ (Bh+Bl)^T, B stored [Npad,512] row-major (K-major).
// Block 128x128, 8 warps a 32x64, K-chunks of 32, cp.async double buffer.
// smem tile: 128 rows x 40 bf16 (80B row stride, 16B-bank conflict-free).
// mode 0: C = acc + bias ; mode 2: += aux[(gm&63)*2048+gn] too
// mode 1: fc epilogue (mask by d_dec, reorder [t*64+b] -> out[b,t,v])
#define TSTR 10240            // one tile (128*80)
#define STGB 40960            // 4 tiles per stage

__global__ void __launch_bounds__(256) gemm_mma(
    const __nv_bfloat16* __restrict__ Ah, const __nv_bfloat16* __restrict__ Al,
    const __nv_bfloat16* __restrict__ Bh, const __nv_bfloat16* __restrict__ Bl,
    const float* __restrict__ bias, float* __restrict__ C, int ldc,
    int Mvalid, int Nvalid, int mode, float* __restrict__ outp,
    const float* __restrict__ aux) {
    extern __shared__ __align__(128) char smem[];
    uint32_t sb = smem_u32(smem);
    int tid = threadIdx.x, lane = tid & 31, wid = tid >> 5;
    int m0 = blockIdx.y * 128, n0 = blockIdx.x * 128;

    const __nv_bfloat16* srcs[4] = {
        Ah + (ll)m0 * Dz, Al + (ll)m0 * Dz,
        Bh + (ll)n0 * Dz, Bl + (ll)n0 * Dz};

    auto issue = [&](int c, int stg) {
        int k0 = c * 32;
#pragma unroll
        for (int it = 0; it < 8; it++) {
            int idx = it * 256 + tid;
            int t4 = idx >> 9, w = idx & 511, row = w >> 2, seg = w & 3;
            uint32_t s = sb + stg * STGB + t4 * TSTR + row * 80 + seg * 16;
            const __nv_bfloat16* g = srcs[t4] + (ll)row * Dz + k0 + seg * 8;
            CPA16(s, g);
        }
        CPA_COMMIT();
    };

    float acc[2][8][4];
#pragma unroll
    for (int i = 0; i < 2; i++)
#pragma unroll
        for (int j = 0; j < 8; j++)
#pragma unroll
            for (int k = 0; k < 4; k++) acc[i][j][k] = 0.f;

    int wm = (wid >> 1) * 32, wn = (wid & 1) * 64;
    int q = lane >> 3, r = lane & 7;
    // a quads: (m0..7,k0),(m8..15,k0),(m0..7,k8),(m8..15,k8)
    uint32_t aoff = (uint32_t)((wm + (q & 1) * 8 + r) * 80 + (q >> 1) * 16);
    // b quads: (n0..7,k0),(n0..7,k8),(n8..15,k0),(n8..15,k8)
    uint32_t boff = (uint32_t)((wn + (q >> 1) * 8 + r) * 80 + (q & 1) * 16);

    issue(0, 0);
    for (int c = 0; c < 16; c++) {
        if (c + 1 < 16) { issue(c + 1, (c + 1) & 1); CPA_WAIT1(); }
        else            { CPA_WAIT0(); }
        __syncthreads();
        uint32_t st = sb + (c & 1) * STGB;
#pragma unroll
        for (int kk = 0; kk < 2; kk++) {
            uint32_t kb = kk * 32;  // 16 bf16 = 32B
            uint32_t ah[2][4], al2[2][4];
            LDMX4(ah[0],  st + aoff + kb);
            LDMX4(ah[1],  st + aoff + 16 * 80 + kb);
            LDMX4(al2[0], st + TSTR + aoff + kb);
            LDMX4(al2[1], st + TSTR + aoff + 16 * 80 + kb);
#pragma unroll
            for (int nh = 0; nh < 4; nh++) {
                uint32_t bh[4], bl2[4];
                LDMX4(bh,  st + 2 * TSTR + boff + nh * 16 * 80 + kb);
                LDMX4(bl2, st + 3 * TSTR + boff + nh * 16 * 80 + kb);
#pragma unroll
                for (int mi = 0; mi < 2; mi++) {
                    MMA_BF16(acc[mi][2 * nh],     ah[mi],  bh[0],  bh[1]);
                    MMA_BF16(acc[mi][2 * nh],     ah[mi],  bl2[0], bl2[1]);
                    MMA_BF16(acc[mi][2 * nh],     al2[mi], bh[0],  bh[1]);
                    MMA_BF16(acc[mi][2 * nh + 1], ah[mi],  bh[2],  bh[3]);
                    MMA_BF16(acc[mi][2 * nh + 1], ah[mi],  bl2[2], bl2[3]);
                    MMA_BF16(acc[mi][2 * nh + 1], al2[mi], bh[2],  bh[3]);
                }
            }
        }
        __syncthreads();
    }

    // epilogue
    int r2 = lane >> 2, c2 = (lane & 3) * 2;
#pragma unroll
    for (int mi = 0; mi < 2; mi++) {
#pragma unroll
        for (int ni = 0; ni < 8; ni++) {
            int gn = n0 + wn + ni * 8 + c2;
            bool ncol = (gn < Nvalid);  // gn, Nvalid both even
            float bv0 = 0.f, bv1 = 0.f;
            if (bias && ncol) { bv0 = bias[gn]; bv1 = bias[gn + 1]; }
#pragma unroll
            for (int hh = 0; hh < 2; hh++) {
                int gm = m0 + wm + mi * 16 + r2 + hh * 8;
                float v0 = acc[mi][ni][2 * hh]     + bv0;
                float v1 = acc[mi][ni][2 * hh + 1] + bv1;
                if (mode == 1) {
                    int tt = gm >> 6, bb = gm & 63;
                    if (tt < Tz && ncol) {
                        if (tt >= d_dec[bb]) { v0 = 0.f; v1 = 0.f; }
                        float2 v = {v0, v1};
                        *(float2*)(outp + ((ll)bb * Tz + tt) * Vz + gn) = v;
                    }
                } else if (gm < Mvalid && ncol) {
                    if (mode == 2) {
                        int bb = gm & 63;
                        v0 += aux[bb * G4 + gn];
                        v1 += aux[bb * G4 + gn + 1];
                    }
                    float2 v = {v0, v1};
                    *(float2*)(C + (ll)gm * ldc + gn) = v;
                }
            }
        }
    }
}

// ------------------------- per-step kernels --------------------------------
__global__ void __launch_bounds__(256) k_hproj(const float* __restrict__ daW,
                                               const float* __restrict__ dab,
                                               const float* __restrict__ fbW,
                                               const float* __restrict__ fbb) {
    __shared__ float hs[16 * Dz];
    int j0 = blockIdx.x * 64;
    int b0 = blockIdx.y * 16;
    int tid = threadIdx.x;
    for (int i = tid; i < (16 * Dz) / 4; i += 256)
        ((float4*)hs)[i] = ((const float4*)(d_h + b0 * Dz))[i];
    __syncthreads();
    int jl = tid & 63, bq = tid >> 6;
    int j = j0 + jl;
    const float* W;
    float bias;
    if (j < Dz) { W = daW + j; bias = dab[j]; }
    else        { W = fbW + (j - Dz); bias = fbb[j - Dz]; }
    float a0 = bias, a1 = bias, a2 = bias, a3 = bias;
#pragma unroll 4
    for (int k = 0; k < Dz; k++) {
        float w = W[k * Dz];
        a0 = fmaf(hs[bq * Dz + k], w, a0);
        a1 = fmaf(hs[(bq + 4) * Dz + k], w, a1);
        a2 = fmaf(hs[(bq + 8) * Dz + k], w, a2);
        a3 = fmaf(hs[(bq + 12) * Dz + k], w, a3);
    }
    d_hg[(b0 + bq) * 1024 + j] = a0;
    d_hg[(b0 + bq + 4) * 1024 + j] = a1;
    d_hg[(b0 + bq + 8) * 1024 + j] = a2;
    d_hg[(b0 + bq + 12) * 1024 + j] = a3;
}

__global__ void __launch_bounds__(256) k_attn(const float* __restrict__ faw,
                                              const float* __restrict__ fabp) {
    __shared__ float att2s[Dz];
    __shared__ float ws[Dz];
    __shared__ float es[Pz];
    __shared__ float red[8];
    int b = blockIdx.x, tid = threadIdx.x;
    int wp = tid >> 5, ln = tid & 31;
    float fab = fabp[0];
    for (int i = tid; i < Dz; i += 256) {
        att2s[i] = d_hg[b * 1024 + i];
        ws[i] = faw[i];
    }
    __syncthreads();
    for (int p = wp; p < Pz; p += 8) {
        const float* row = d_att1 + (ll)(b * Pz + p) * Dz;
        float s = 0.f;
#pragma unroll 4
        for (int a = ln; a < Dz; a += 32)
            s = fmaf(fmaxf(row[a] + att2s[a], 0.f), ws[a], s);
#pragma unroll
        for (int o = 16; o > 0; o >>= 1) s += __shfl_down_sync(0xffffffffu, s, o);
        if (ln == 0) es[p] = s + fab;
    }
    __syncthreads();
    float v = (tid < Pz) ? es[tid] : -3.4e38f;
#pragma unroll
    for (int o = 16; o > 0; o >>= 1) v = fmaxf(v, __shfl_down_sync(0xffffffffu, v, o));
    if (ln == 0) red[wp] = v;
    __syncthreads();
    if (tid == 0) {
        float m = red[0];
        for (int i = 1; i < 8; i++) m = fmaxf(m, red[i]);
        red[0] = m;
    }
    __syncthreads();
    float MX = red[0];
    float ex = (tid < Pz) ? __expf(es[tid] - MX) : 0.f;
    __syncthreads();
    float s = ex;
#pragma unroll
    for (int o = 16; o > 0; o >>= 1) s += __shfl_down_sync(0xffffffffu, s, o);
    if (ln == 0) red[wp] = s;
    __syncthreads();
    if (tid == 0) {
        float t2 = 0.f;
        for (int i = 0; i < 8; i++) t2 += red[i];
        red[0] = t2;
    }
    __syncthreads();
    float inv = 1.f / red[0];
    if (tid < Pz) es[tid] = ex * inv;
    __syncthreads();
    for (int e = tid; e < Dz; e += 256) {
        float a = 0.f;
#pragma unroll 4
        for (int p = 0; p < Pz; p++)
            a = fmaf(d_enc_s[(ll)(b * Pz + p) * Dz + e], es[p], a);
        float g = sigf(d_hg[b * 1024 + Dz + e]);
        d_awe[b * Dz + e] = g * a;
    }
}

__global__ void __launch_bounds__(256) k_lstm(int t) {
    extern __shared__ float sm[];  // as_[16*512] | hs[16*512] = 64KB
    float* as_ = sm;
    float* hs = sm + 16 * Dz;
    int j0 = blockIdx.x * 64;
    int b0 = blockIdx.y * 16;
    int tid = threadIdx.x;
    for (int i = tid; i < (16 * Dz) / 4; i += 256) {
        ((float4*)as_)[i] = ((const float4*)(d_awe + b0 * Dz))[i];
        ((float4*)hs)[i] = ((const float4*)(d_h + b0 * Dz))[i];
    }
    __syncthreads();
    int jl = tid & 63, bq = tid >> 6;
    int j = j0 + jl;
    const float* wa = d_WihT + (ll)Dz * G4 + j;
    const float* wh = d_WhhT + j;
    float a0 = 0.f, a1 = 0.f, a2 = 0.f, a3 = 0.f;
#pragma unroll 2
    for (int k = 0; k < Dz; k++) {
        float w1 = wa[(ll)k * G4];
        float w2 = wh[(ll)k * G4];
        a0 = fmaf(as_[bq * Dz + k], w1, a0);
        a0 = fmaf(hs[bq * Dz + k], w2, a0);
        a1 = fmaf(as_[(bq + 4) * Dz + k], w1, a1);
        a1 = fmaf(hs[(bq + 4) * Dz + k], w2, a1);
        a2 = fmaf(as_[(bq + 8) * Dz + k], w1, a2);
        a2 = fmaf(hs[(bq + 8) * Dz + k], w2, a2);
        a3 = fmaf(as_[(bq + 12) * Dz + k], w1, a3);
        a3 = fmaf(hs[(bq + 12) * Dz + k], w2, a3);
    }
    int base = t * Bz + b0;
    d_gates[(b0 + bq) * G4 + j]      = d_pre[(ll)(base + bq) * G4 + j] + a0;
    d_gates[(b0 + bq + 4) * G4 + j]  = d_pre[(ll)(base + bq + 4) * G4 + j] + a1;
    d_gates[(b0 + bq + 8) * G4 + j]  = d_pre[(ll)(base + bq + 8) * G4 + j] + a2;
    d_gates[(b0 + bq + 12) * G4 + j] = d_pre[(ll)(base + bq + 12) * G4 + j] + a3;
}

__global__ void k_cell(int t) {
    int b = blockIdx.x, j = threadIdx.x;
    const float* g = d_gates + b * G4;
    float i_ = sigf(g[j]);
    float f_ = sigf(g[Dz + j]);
    float gg = tanhf(g[2 * Dz + j]);
    float o_ = sigf(g[3 * Dz + j]);
    float c0 = d_c[b * Dz + j];
    float cn = f_ * c0 + i_ * gg;
    float hn = o_ * tanhf(cn);
    ll ro = (ll)(t * Bz + b) * Dz + j;
    __nv_bfloat16 h16 = __float2bfloat16(hn);
    d_HallA_h[ro] = h16;
    d_HallA_l[ro] = __float2bfloat16(hn - __bfloat162float(h16));
    if (t < d_dec[b]) {
        d_h[b * Dz + j] = hn;
        d_c[b * Dz + j] = cn;
    }
}

// ------------------------- host launcher -----------------------------------
extern "C" void kernel_launch(void* const* d_in, const int* in_sizes, int n_in,
                              void* d_out, int out_size) {
    const float* enc_out = (const float*)d_in[0];
    const int* caps_in = (const int*)d_in[1];
    const int* cap_len = (const int*)d_in[2];
    const int* class_k = (const int*)d_in[3];
    const float* embW = (const float*)d_in[4];
    const float* clsW = (const float*)d_in[5];
    const float* eaW = (const float*)d_in[6];
    const float* eab = (const float*)d_in[7];
    const float* daW = (const float*)d_in[8];
    const float* dab = (const float*)d_in[9];
    const float* faw = (const float*)d_in[10];
    const float* fab = (const float*)d_in[11];
    const float* ihW = (const float*)d_in[12];
    const float* ihb = (const float*)d_in[13];
    const float* icW = (const float*)d_in[14];
    const float* icb = (const float*)d_in[15];
    const float* fbW = (const float*)d_in[16];
    const float* fbb = (const float*)d_in[17];
    const float* Wih = (const float*)d_in[18];
    const float* Whh = (const float*)d_in[19];
    const float* bih = (const float*)d_in[20];
    const float* bhh = (const float*)d_in[21];
    const float* fcW = (const float*)d_in[22];
    const float* fcb = (const float*)d_in[23];
    float* out = (float*)d_out;
    ll osz = out_size;

    cudaFuncSetAttribute(gemm_mma, cudaFuncAttributeMaxDynamicSharedMemorySize,
                         2 * STGB);
    cudaFuncSetAttribute(k_lstm, cudaFuncAttributeMaxDynamicSharedMemorySize,
                         32 * Dz * 4);

    float *p_att1, *p_WihT, *p_pre, *p_cls, *p_clspre, *p_biasc;
    __nv_bfloat16 *p_encAh, *p_encAl, *p_embAh, *p_embAl, *p_HallAh, *p_HallAl;
    __nv_bfloat16 *p_attBh, *p_attBl, *p_wihBh, *p_wihBl, *p_fcBh, *p_fcBl;
    cudaGetSymbolAddress((void**)&p_att1, d_att1);
    cudaGetSymbolAddress((void**)&p_WihT, d_WihT);
    cudaGetSymbolAddress((void**)&p_pre, d_pre);
    cudaGetSymbolAddress((void**)&p_cls, d_cls);
    cudaGetSymbolAddress((void**)&p_clspre, d_clspre);
    cudaGetSymbolAddress((void**)&p_biasc, d_biasc);
    cudaGetSymbolAddress((void**)&p_encAh, d_encA_h);
    cudaGetSymbolAddress((void**)&p_encAl, d_encA_l);
    cudaGetSymbolAddress((void**)&p_embAh, d_embA_h);
    cudaGetSymbolAddress((void**)&p_embAl, d_embA_l);
    cudaGetSymbolAddress((void**)&p_HallAh, d_HallA_h);
    cudaGetSymbolAddress((void**)&p_HallAl, d_HallA_l);
    cudaGetSymbolAddress((void**)&p_attBh, d_attB_h);
    cudaGetSymbolAddress((void**)&p_attBl, d_attB_l);
    cudaGetSymbolAddress((void**)&p_wihBh, d_wihB_h);
    cudaGetSymbolAddress((void**)&p_wihBl, d_wihB_l);
    cudaGetSymbolAddress((void**)&p_fcBh, d_fcB_h);
    cudaGetSymbolAddress((void**)&p_fcBl, d_fcB_l);

    k_sort<<<1, Bz>>>(cap_len, out, osz);
    k_gather_enc<<<512, 256>>>(enc_out);
    k_gather_misc<<<Bz, Dz>>>(caps_in, class_k, clsW, out, osz);
    k_init<<<Bz, Dz>>>(ihW, ihb, icW, icb);

    k_embs<<<256, 256>>>(embW);
    k_padzero<<<64, 256>>>();
    k_transpose<<<512, 256>>>(Wih, Whh);
    k_cvt_wih<<<256, 256>>>(Wih);
    k_cvtT<<<dim3(16, 16), dim3(32, 8)>>>(eaW, Dz, p_attBh, p_attBl);
    k_cvtT<<<dim3(NPAD_FC / 32, 16), dim3(32, 8)>>>(fcW, Vz, p_fcBh, p_fcBl);
    k_biasc<<<8, 256>>>(bih, bhh);

    // cls_pre = cls_emb @ WihT[1024:1536] : [64,2048]
    gemm128<<<dim3(16, 1), 256>>>(p_cls, Dz, p_WihT + (ll)1024 * G4, G4,
                                  nullptr, p_clspre, G4, Bz, G4, Dz);

    // att1 = enc_s @ enc_att_W + b : [12544,512]
    gemm_mma<<<dim3(4, 98), 256, 2 * STGB>>>(p_encAh, p_encAl, p_attBh, p_attBl,
                                             eab, p_att1, Dz, Bz * Pz, Dz, 0,
                                             nullptr, nullptr);
    // pre_gates = embs @ Wih_emb^T + cls_pre + bih + bhh : [3264,2048]
    gemm_mma<<<dim3(16, 26), 256, 2 * STGB>>>(p_embAh, p_embAl, p_wihBh, p_wihBl,
                                              p_biasc, p_pre, G4, Tz * Bz, G4, 2,
                                              nullptr, p_clspre);

    for (int t = 0; t < Tz; t++) {
        k_hproj<<<dim3(16, 4), 256>>>(daW, dab, fbW, fbb);
        k_attn<<<Bz, 256>>>(faw, fab);
        k_lstm<<<dim3(32, 4), 256, 32 * Dz * 4>>>(t);
        k_cell<<<Bz, Dz>>>(t);
    }

    // predictions = mask(Hall @ fc_W + fc_b) -> out[b,t,v]
    gemm_mma<<<dim3(NPAD_FC / 128, 26), 256, 2 * STGB>>>(
        p_HallAh, p_HallAl, p_fcBh, p_fcBl, fcb, nullptr, 0,
        Tz * Bz, Vz, 1, out, nullptr);
}

// round 7
// speedup vs baseline: 1.0419x; 1.0419x over previous
#include <cuda_runtime.h>
#include <cstdint>
#include <math.h>

#define Bz 64
#define Pz 196
#define Dz 512
#define Vz 10000
#define MAXLEN 52
#define Tz 51
#define G4 2048
#define MPAD 3328          // 26*128

typedef long long ll;

static const ll OFF_CAPS = (ll)Bz * Tz * Vz;
static const ll OFF_DEC  = OFF_CAPS + (ll)Bz * MAXLEN;
static const ll OFF_SI   = OFF_DEC + Bz;

// ------------------------- device scratch ---------------------------------
__device__ float d_enc_s[Bz * Pz * Dz];
__device__ float d_att1[Bz * Pz * Dz];
__device__ float d_cls[Bz * Dz];
__device__ float d_h[Bz * Dz];
__device__ float d_c[Bz * Dz];
__device__ float d_hg[Bz * 1024];
__device__ float d_awe[Bz * Dz];
__device__ float d_pre[(ll)MPAD * G4];
__device__ float d_clspre[Bz * G4];
__device__ float d_gates[Bz * G4];
__device__ float d_WihT[1536 * G4];   // WihT[k][j] = Wih[j][k]
__device__ float d_WhhT[Dz * G4];
__device__ float d_biasc[G4];
__device__ float d_embsC[(ll)MPAD * Dz];  // compacted embeddings
__device__ float d_Hall[(ll)MPAD * Dz];   // compacted hidden states
__device__ int   d_sort[Bz];
__device__ int   d_dec[Bz];
__device__ int   d_caps[Bz * MAXLEN];
__device__ int   d_start[Bz + 1];     // d_start[Bz] = A_total
__device__ int   d_nt[Tz];            // active-batch count per step
__device__ int   d_rowb[MPAD];
__device__ int   d_rowt[MPAD];

__device__ __forceinline__ float sigf(float x) { return 1.f / (1.f + __expf(-x)); }

// ------------------------- setup kernels ----------------------------------
__global__ void k_sort(const int* __restrict__ cap_len, float* __restrict__ out,
                       ll out_size) {
    __shared__ int ls[Bz];
    __shared__ int sd[Bz];
    int tid = threadIdx.x;
    ls[tid] = cap_len[tid];
    __syncthreads();
    int my = ls[tid];
    int rank = 0;
    for (int j = 0; j < Bz; j++) {
        int lj = ls[j];
        if (lj > my || (lj == my && j < tid)) rank++;
    }
    d_sort[rank] = tid;
    d_dec[rank]  = my - 1;
    sd[rank] = my - 1;
    if (OFF_SI + Bz <= out_size) {
        out[OFF_DEC + rank] = (float)(my - 1);
        out[OFF_SI + rank]  = (float)tid;
    }
    __syncthreads();
    // n_t = #{b : dec[b] > t}
    if (tid < Tz) {
        int c = 0;
        for (int b = 0; b < Bz; b++) c += (sd[b] > tid) ? 1 : 0;
        d_nt[tid] = c;
    }
    // start_b = prefix sum of dec
    int s = 0;
    for (int b = 0; b < tid; b++) s += sd[b];
    d_start[tid] = s;
    if (tid == Bz - 1) d_start[Bz] = s + sd[tid];
}

__global__ void k_rowinit() {
    int idx = blockIdx.x * 256 + threadIdx.x;
    if (idx < MPAD) { d_rowb[idx] = -1; d_rowt[idx] = 0; }
}

__global__ void k_rowmap() {
    int b = blockIdx.x, t = threadIdx.x;  // 64 threads
    if (t < d_dec[b]) {
        int r = d_start[b] + t;
        d_rowb[r] = b;
        d_rowt[r] = t;
    }
}

__global__ void k_gather_enc(const float* __restrict__ enc_in) {
    int n = Bz * Pz * Dz;
    for (int idx = blockIdx.x * blockDim.x + threadIdx.x; idx < n;
         idx += gridDim.x * blockDim.x) {
        int b = idx / (Pz * Dz);
        int r = idx - b * (Pz * Dz);
        d_enc_s[idx] = enc_in[(ll)d_sort[b] * (Pz * Dz) + r];
    }
}

__global__ void k_gather_misc(const int* __restrict__ caps_in,
                              const int* __restrict__ class_k,
                              const float* __restrict__ clsW,
                              float* __restrict__ out, ll out_size) {
    int b = blockIdx.x;
    int e = threadIdx.x;  // 512
    d_cls[b * Dz + e] = clsW[(ll)class_k[b] * Dz + e];
    if (e < MAXLEN) {
        int v = caps_in[d_sort[b] * MAXLEN + e];
        d_caps[b * MAXLEN + e] = v;
        if (OFF_CAPS + (ll)Bz * MAXLEN <= out_size)
            out[OFF_CAPS + b * MAXLEN + e] = (float)v;
    }
}

__global__ void k_init(const float* __restrict__ ihW, const float* __restrict__ ihb,
                       const float* __restrict__ icW, const float* __restrict__ icb) {
    __shared__ float s[1024];
    int b = blockIdx.x, j = threadIdx.x;
    float s0 = 0.f, s1 = 0.f, s2 = 0.f, s3 = 0.f;
#pragma unroll 4
    for (int p = 0; p < 196; p += 4) {
        s0 += d_enc_s[(b * Pz + p) * Dz + j];
        s1 += d_enc_s[(b * Pz + p + 1) * Dz + j];
        s2 += d_enc_s[(b * Pz + p + 2) * Dz + j];
        s3 += d_enc_s[(b * Pz + p + 3) * Dz + j];
    }
    s[j] = (s0 + s1 + s2 + s3) * (1.f / 196.f);
    s[Dz + j] = d_cls[b * Dz + j];
    __syncthreads();
    float ah0 = ihb[j], ah1 = 0.f, ac0 = icb[j], ac1 = 0.f;
#pragma unroll 4
    for (int k = 0; k < 1024; k += 2) {
        float x0 = s[k], x1 = s[k + 1];
        ah0 = fmaf(x0, ihW[k * Dz + j], ah0);
        ac0 = fmaf(x0, icW[k * Dz + j], ac0);
        ah1 = fmaf(x1, ihW[(k + 1) * Dz + j], ah1);
        ac1 = fmaf(x1, icW[(k + 1) * Dz + j], ac1);
    }
    d_h[b * Dz + j] = ah0 + ah1;
    d_c[b * Dz + j] = ac0 + ac1;
}

__global__ void k_embs(const float* __restrict__ embW) {
    ll n = (ll)MPAD * Dz;
    for (ll idx = blockIdx.x * blockDim.x + threadIdx.x; idx < n;
         idx += (ll)gridDim.x * blockDim.x) {
        int r = (int)(idx / Dz), k = (int)(idx - (ll)r * Dz);
        int b = d_rowb[r];
        if (b < 0) continue;
        int tok = d_caps[b * MAXLEN + d_rowt[r]];
        d_embsC[idx] = embW[(ll)tok * Dz + k];
    }
}

__global__ void k_transpose(const float* __restrict__ Wih,
                            const float* __restrict__ Whh) {
    int n1 = 1536 * G4;
    int n = n1 + Dz * G4;
    for (int idx = blockIdx.x * blockDim.x + threadIdx.x; idx < n;
         idx += gridDim.x * blockDim.x) {
        if (idx < n1) {
            int k = idx / G4, j = idx - k * G4;
            d_WihT[idx] = Wih[(ll)j * 1536 + k];
        } else {
            int i2 = idx - n1;
            int k = i2 / G4, j = i2 - k * G4;
            d_WhhT[i2] = Whh[(ll)j * Dz + k];
        }
    }
}

__global__ void k_biasc(const float* __restrict__ bih, const float* __restrict__ bhh) {
    int j = blockIdx.x * 256 + threadIdx.x;
    if (j < G4) d_biasc[j] = bih[j] + bhh[j];
}

// zero masked output rows (out poisoned to 0xAA)
__global__ void k_zerofill(float* __restrict__ out) {
    int t = blockIdx.x, b = blockIdx.y;
    if (t < d_dec[b]) return;
    float4* p = (float4*)(out + ((ll)b * Tz + t) * Vz);
    float4 z = {0.f, 0.f, 0.f, 0.f};
    for (int i = threadIdx.x; i < Vz / 4; i += 256) p[i] = z;
}

// ------------------------- SIMT GEMM (cls_pre only) ------------------------
__global__ void __launch_bounds__(256) gemm128(
    const float* __restrict__ A, int lda, const float* __restrict__ Bm, int ldb,
    const float* __restrict__ bias, float* __restrict__ C, int ldc,
    int M, int N, int K) {
    __shared__ float As[8][128];
    __shared__ float Bs[8][128];
    int tid = threadIdx.x;
    int n0 = blockIdx.x * 128, m0 = blockIdx.y * 128;
    int tx = tid & 15, ty = tid >> 4;
    float acc[8][8];
#pragma unroll
    for (int i = 0; i < 8; i++)
#pragma unroll
        for (int j = 0; j < 8; j++) acc[i][j] = 0.f;
    int lm = tid >> 1, lkq = (tid & 1) * 4, lk = tid >> 5, ln4 = (tid & 31) * 4;
    for (int k0 = 0; k0 < K; k0 += 8) {
        float4 va = make_float4(0.f, 0.f, 0.f, 0.f);
        int gm = m0 + lm;
        if (gm < M) va = *(const float4*)(A + (ll)gm * lda + k0 + lkq);
        float4 vb = make_float4(0.f, 0.f, 0.f, 0.f);
        int gn = n0 + ln4;
        if (gn + 3 < N) vb = *(const float4*)(Bm + (ll)(k0 + lk) * ldb + gn);
        __syncthreads();
        As[lkq + 0][lm] = va.x; As[lkq + 1][lm] = va.y;
        As[lkq + 2][lm] = va.z; As[lkq + 3][lm] = va.w;
        *(float4*)&Bs[lk][ln4] = vb;
        __syncthreads();
#pragma unroll
        for (int kk = 0; kk < 8; kk++) {
            float4 A0 = *(const float4*)&As[kk][ty * 8];
            float4 A1 = *(const float4*)&As[kk][ty * 8 + 4];
            float4 B0 = *(const float4*)&Bs[kk][tx * 8];
            float4 B1 = *(const float4*)&Bs[kk][tx * 8 + 4];
            float ar[8] = {A0.x, A0.y, A0.z, A0.w, A1.x, A1.y, A1.z, A1.w};
            float br[8] = {B0.x, B0.y, B0.z, B0.w, B1.x, B1.y, B1.z, B1.w};
#pragma unroll
            for (int i = 0; i < 8; i++)
#pragma unroll
                for (int j = 0; j < 8; j++) acc[i][j] = fmaf(ar[i], br[j], acc[i][j]);
        }
    }
#pragma unroll
    for (int i = 0; i < 8; i++) {
        int gm = m0 + ty * 8 + i;
        if (gm >= M) continue;
#pragma unroll
        for (int j = 0; j < 8; j++) {
            int gn = n0 + tx * 8 + j;
            if (gn >= N) continue;
            C[(ll)gm * ldc + gn] = acc[i][j] + (bias ? bias[gn] : 0.f);
        }
    }
}

// ------------------------- conflict-free FFMA GEMM (K=512) -----------------
// C[M,N] = A[M,512] @ B[512,N] (+bias). Quadrant float4 fragments: lanes read
// 16B slots at tx*16 / ty*16 -> 8 distinct slots per phase, no LDS conflicts.
// mode 0: plain store.  mode 2: compacted rows, +bias[gn]+aux[rowb*2048+gn].
// mode 1: fc epilogue, compacted rows -> out[(rowb*51+rowt)*Vz + gn].
__global__ void __launch_bounds__(256) gemm2(
    const float* __restrict__ A, int lda, const float* __restrict__ Bm, int ldb,
    const float* __restrict__ bias, float* __restrict__ C, int ldc,
    int M, int N, int mode, float* __restrict__ outp,
    const float* __restrict__ aux) {
    __shared__ float As[8][128];
    __shared__ float Bs[8][128];
    int tid = threadIdx.x;
    int n0 = blockIdx.x * 128, m0 = blockIdx.y * 128;
    if (mode != 0 && m0 >= d_start[Bz]) return;  // compacted-row early exit
    int tx = tid & 15, ty = tid >> 4;
    float acc[2][2][4][4];
#pragma unroll
    for (int a = 0; a < 2; a++)
#pragma unroll
        for (int b = 0; b < 2; b++)
#pragma unroll
            for (int i = 0; i < 4; i++)
#pragma unroll
                for (int j = 0; j < 4; j++) acc[a][b][i][j] = 0.f;
    int lm = tid >> 1, lkq = (tid & 1) * 4, lk = tid >> 5, ln4 = (tid & 31) * 4;
    for (int k0 = 0; k0 < Dz; k0 += 8) {
        float4 va = make_float4(0.f, 0.f, 0.f, 0.f);
        int gm = m0 + lm;
        if (gm < M) va = *(const float4*)(A + (ll)gm * lda + k0 + lkq);
        float4 vb = make_float4(0.f, 0.f, 0.f, 0.f);
        int gn = n0 + ln4;
        if (gn + 3 < N) vb = *(const float4*)(Bm + (ll)(k0 + lk) * ldb + gn);
        __syncthreads();
        As[lkq + 0][lm] = va.x; As[lkq + 1][lm] = va.y;
        As[lkq + 2][lm] = va.z; As[lkq + 3][lm] = va.w;
        *(float4*)&Bs[lk][ln4] = vb;
        __syncthreads();
#pragma unroll
        for (int kk = 0; kk < 8; kk++) {
            float4 a0 = *(const float4*)&As[kk][ty * 4];
            float4 a1 = *(const float4*)&As[kk][64 + ty * 4];
            float4 b0 = *(const float4*)&Bs[kk][tx * 4];
            float4 b1 = *(const float4*)&Bs[kk][64 + tx * 4];
            float ar[2][4] = {{a0.x, a0.y, a0.z, a0.w}, {a1.x, a1.y, a1.z, a1.w}};
            float br[2][4] = {{b0.x, b0.y, b0.z, b0.w}, {b1.x, b1.y, b1.z, b1.w}};
#pragma unroll
            for (int mi = 0; mi < 2; mi++)
#pragma unroll
                for (int i = 0; i < 4; i++)
#pragma unroll
                    for (int ni = 0; ni < 2; ni++)
#pragma unroll
                        for (int j = 0; j < 4; j++)
                            acc[mi][ni][i][j] =
                                fmaf(ar[mi][i], br[ni][j], acc[mi][ni][i][j]);
        }
    }
    // epilogue: float4 coalesced stores
#pragma unroll
    for (int mi = 0; mi < 2; mi++) {
#pragma unroll
        for (int i = 0; i < 4; i++) {
            int gm = m0 + mi * 64 + ty * 4 + i;
            int bb = 0, tt = 0;
            bool rowok;
            if (mode == 0) {
                rowok = (gm < M);
            } else {
                bb = d_rowb[gm];
                tt = d_rowt[gm];
                rowok = (bb >= 0);
            }
            if (!rowok) continue;
#pragma unroll
            for (int ni = 0; ni < 2; ni++) {
                int gn = n0 + ni * 64 + tx * 4;
                if (gn >= N) continue;  // gn, N multiples of 4
                float4 v;
                v.x = acc[mi][ni][i][0]; v.y = acc[mi][ni][i][1];
                v.z = acc[mi][ni][i][2]; v.w = acc[mi][ni][i][3];
                if (bias) {
                    float4 bv = *(const float4*)(bias + gn);
                    v.x += bv.x; v.y += bv.y; v.z += bv.z; v.w += bv.w;
                }
                if (mode == 2) {
                    float4 ax = *(const float4*)(aux + (ll)bb * G4 + gn);
                    v.x += ax.x; v.y += ax.y; v.z += ax.z; v.w += ax.w;
                }
                if (mode == 1)
                    *(float4*)(outp + ((ll)bb * Tz + tt) * Vz + gn) = v;
                else
                    *(float4*)(C + (ll)gm * ldc + gn) = v;
            }
        }
    }
}

// ------------------------- per-step kernels --------------------------------
__global__ void __launch_bounds__(256) k_hproj(int t,
                                               const float* __restrict__ daW,
                                               const float* __restrict__ dab,
                                               const float* __restrict__ fbW,
                                               const float* __restrict__ fbb) {
    __shared__ float hs[8 * Dz];
    int b0 = blockIdx.y * 8;
    if (b0 >= d_nt[t]) return;
    int j0 = blockIdx.x * 64;
    int tid = threadIdx.x;
    for (int i = tid; i < (8 * Dz) / 4; i += 256)
        ((float4*)hs)[i] = ((const float4*)(d_h + b0 * Dz))[i];
    __syncthreads();
    int jl = tid & 63, bq = tid >> 6;
    int j = j0 + jl;
    const float* W;
    float bias;
    if (j < Dz) { W = daW + j; bias = dab[j]; }
    else        { W = fbW + (j - Dz); bias = fbb[j - Dz]; }
    float a0 = bias, a1 = bias;
#pragma unroll 4
    for (int k = 0; k < Dz; k++) {
        float w = W[k * Dz];
        a0 = fmaf(hs[bq * Dz + k], w, a0);
        a1 = fmaf(hs[(bq + 4) * Dz + k], w, a1);
    }
    d_hg[(b0 + bq) * 1024 + j] = a0;
    d_hg[(b0 + bq + 4) * 1024 + j] = a1;
}

__global__ void __launch_bounds__(256) k_attn(int t,
                                              const float* __restrict__ faw,
                                              const float* __restrict__ fabp) {
    __shared__ float att2s[Dz];
    __shared__ float ws[Dz];
    __shared__ float es[Pz];
    __shared__ float red[8];
    int b = blockIdx.x;
    if (b >= d_nt[t]) return;
    int tid = threadIdx.x;
    int wp = tid >> 5, ln = tid & 31;
    float fab = fabp[0];
    for (int i = tid; i < Dz; i += 256) {
        att2s[i] = d_hg[b * 1024 + i];
        ws[i] = faw[i];
    }
    __syncthreads();
    for (int p = wp; p < Pz; p += 8) {
        const float* row = d_att1 + (ll)(b * Pz + p) * Dz;
        float s = 0.f;
#pragma unroll 4
        for (int a = ln; a < Dz; a += 32)
            s = fmaf(fmaxf(row[a] + att2s[a], 0.f), ws[a], s);
#pragma unroll
        for (int o = 16; o > 0; o >>= 1) s += __shfl_down_sync(0xffffffffu, s, o);
        if (ln == 0) es[p] = s + fab;
    }
    __syncthreads();
    float v = (tid < Pz) ? es[tid] : -3.4e38f;
#pragma unroll
    for (int o = 16; o > 0; o >>= 1) v = fmaxf(v, __shfl_down_sync(0xffffffffu, v, o));
    if (ln == 0) red[wp] = v;
    __syncthreads();
    if (tid == 0) {
        float m = red[0];
        for (int i = 1; i < 8; i++) m = fmaxf(m, red[i]);
        red[0] = m;
    }
    __syncthreads();
    float MX = red[0];
    float ex = (tid < Pz) ? __expf(es[tid] - MX) : 0.f;
    __syncthreads();
    float s = ex;
#pragma unroll
    for (int o = 16; o > 0; o >>= 1) s += __shfl_down_sync(0xffffffffu, s, o);
    if (ln == 0) red[wp] = s;
    __syncthreads();
    if (tid == 0) {
        float t2 = 0.f;
        for (int i = 0; i < 8; i++) t2 += red[i];
        red[0] = t2;
    }
    __syncthreads();
    float inv = 1.f / red[0];
    if (tid < Pz) es[tid] = ex * inv;
    __syncthreads();
    for (int e = tid; e < Dz; e += 256) {
        float a = 0.f;
#pragma unroll 4
        for (int p = 0; p < Pz; p++)
            a = fmaf(d_enc_s[(ll)(b * Pz + p) * Dz + e], es[p], a);
        float g = sigf(d_hg[b * 1024 + Dz + e]);
        d_awe[b * Dz + e] = g * a;
    }
}

__global__ void __launch_bounds__(256) k_lstm(int t) {
    __shared__ float as_[8 * Dz];
    __shared__ float hs[8 * Dz];
    int b0 = blockIdx.y * 8;
    if (b0 >= d_nt[t]) return;
    int j0 = blockIdx.x * 64;
    int tid = threadIdx.x;
    for (int i = tid; i < (8 * Dz) / 4; i += 256) {
        ((float4*)as_)[i] = ((const float4*)(d_awe + b0 * Dz))[i];
        ((float4*)hs)[i] = ((const float4*)(d_h + b0 * Dz))[i];
    }
    __syncthreads();
    int jl = tid & 63, bq = tid >> 6;
    int j = j0 + jl;
    const float* wa = d_WihT + (ll)Dz * G4 + j;
    const float* wh = d_WhhT + j;
    float a0 = 0.f, a1 = 0.f;
#pragma unroll 2
    for (int k = 0; k < Dz; k++) {
        float w1 = wa[(ll)k * G4];
        float w2 = wh[(ll)k * G4];
        a0 = fmaf(as_[bq * Dz + k], w1, a0);
        a0 = fmaf(hs[bq * Dz + k], w2, a0);
        a1 = fmaf(as_[(bq + 4) * Dz + k], w1, a1);
        a1 = fmaf(hs[(bq + 4) * Dz + k], w2, a1);
    }
    int r0 = d_start[b0 + bq] + t;
    int r1 = d_start[b0 + bq + 4] + t;
    d_gates[(b0 + bq) * G4 + j] = d_pre[(ll)r0 * G4 + j] + a0;
    d_gates[(b0 + bq + 4) * G4 + j] = d_pre[(ll)r1 * G4 + j] + a1;
}

__global__ void k_cell(int t) {
    int b = blockIdx.x;
    if (b >= d_nt[t]) return;  // b < n_t  <=>  t < dec[b]
    int j = threadIdx.x;
    const float* g = d_gates + b * G4;
    float i_ = sigf(g[j]);
    float f_ = sigf(g[Dz + j]);
    float gg = tanhf(g[2 * Dz + j]);
    float o_ = sigf(g[3 * Dz + j]);
    float c0 = d_c[b * Dz + j];
    float cn = f_ * c0 + i_ * gg;
    float hn = o_ * tanhf(cn);
    d_h[b * Dz + j] = hn;
    d_c[b * Dz + j] = cn;
    int r = d_start[b] + t;
    d_Hall[(ll)r * Dz + j] = hn;
}

// ------------------------- host launcher -----------------------------------
extern "C" void kernel_launch(void* const* d_in, const int* in_sizes, int n_in,
                              void* d_out, int out_size) {
    const float* enc_out = (const float*)d_in[0];
    const int* caps_in = (const int*)d_in[1];
    const int* cap_len = (const int*)d_in[2];
    const int* class_k = (const int*)d_in[3];
    const float* embW = (const float*)d_in[4];
    const float* clsW = (const float*)d_in[5];
    const float* eaW = (const float*)d_in[6];
    const float* eab = (const float*)d_in[7];
    const float* daW = (const float*)d_in[8];
    const float* dab = (const float*)d_in[9];
    const float* faw = (const float*)d_in[10];
    const float* fab = (const float*)d_in[11];
    const float* ihW = (const float*)d_in[12];
    const float* ihb = (const float*)d_in[13];
    const float* icW = (const float*)d_in[14];
    const float* icb = (const float*)d_in[15];
    const float* fbW = (const float*)d_in[16];
    const float* fbb = (const float*)d_in[17];
    const float* Wih = (const float*)d_in[18];
    const float* Whh = (const float*)d_in[19];
    const float* bih = (const float*)d_in[20];
    const float* bhh = (const float*)d_in[21];
    const float* fcW = (const float*)d_in[22];
    const float* fcb = (const float*)d_in[23];
    float* out = (float*)d_out;
    ll osz = out_size;

    float *p_enc_s, *p_att1, *p_WihT, *p_pre, *p_cls, *p_clspre, *p_biasc;
    float *p_embsC, *p_Hall;
    cudaGetSymbolAddress((void**)&p_enc_s, d_enc_s);
    cudaGetSymbolAddress((void**)&p_att1, d_att1);
    cudaGetSymbolAddress((void**)&p_WihT, d_WihT);
    cudaGetSymbolAddress((void**)&p_pre, d_pre);
    cudaGetSymbolAddress((void**)&p_cls, d_cls);
    cudaGetSymbolAddress((void**)&p_clspre, d_clspre);
    cudaGetSymbolAddress((void**)&p_biasc, d_biasc);
    cudaGetSymbolAddress((void**)&p_embsC, d_embsC);
    cudaGetSymbolAddress((void**)&p_Hall, d_Hall);

    // ---- setup ----
    k_sort<<<1, Bz>>>(cap_len, out, osz);
    k_rowinit<<<(MPAD + 255) / 256, 256>>>();
    k_rowmap<<<Bz, Bz>>>();
    k_gather_enc<<<512, 256>>>(enc_out);
    k_gather_misc<<<Bz, Dz>>>(caps_in, class_k, clsW, out, osz);
    k_init<<<Bz, Dz>>>(ihW, ihb, icW, icb);
    k_embs<<<512, 256>>>(embW);
    k_transpose<<<512, 256>>>(Wih, Whh);
    k_biasc<<<8, 256>>>(bih, bhh);
    k_zerofill<<<dim3(Tz, Bz), 256>>>(out);

    // cls_pre = cls_emb @ WihT[1024:1536] : [64,2048]
    gemm128<<<dim3(16, 1), 256>>>(p_cls, Dz, p_WihT + (ll)1024 * G4, G4,
                                  nullptr, p_clspre, G4, Bz, G4, Dz);

    // att1 = enc_s @ enc_att_W + b : [12544,512]
    gemm2<<<dim3(4, 98), 256>>>(p_enc_s, Dz, eaW, Dz, eab, p_att1, Dz,
                                Bz * Pz, Dz, 0, nullptr, nullptr);
    // pre = embsC @ Wih_emb + cls_pre + bih + bhh : [A_total,2048] compacted
    gemm2<<<dim3(16, MPAD / 128), 256>>>(p_embsC, Dz, p_WihT, G4, p_biasc,
                                         p_pre, G4, MPAD, G4, 2, nullptr,
                                         p_clspre);

    // ---- recurrence ----
    for (int t = 0; t < Tz; t++) {
        k_hproj<<<dim3(16, 8), 256>>>(t, daW, dab, fbW, fbb);
        k_attn<<<Bz, 256>>>(t, faw, fab);
        k_lstm<<<dim3(32, 8), 256>>>(t);
        k_cell<<<Bz, Dz>>>(t);
    }

    // predictions (active rows only) = Hall @ fc_W + fc_b -> out[b,t,v]
    gemm2<<<dim3(79, MPAD / 128), 256>>>(p_Hall, Dz, fcW, Vz, fcb, nullptr, 0,
                                         MPAD, Vz, 1, out, nullptr);
}